// round 6
// baseline (speedup 1.0000x reference)
#include <cuda_runtime.h>
#include <cuda_bf16.h>

#define N_NODES 8192
#define IN_DIM  256
#define OUT_DIM 128
#define P_COLS  144   // 128 cols of w*h, col 128 = w, cols 129..143 = 0

// Scratch (device globals: no runtime allocation allowed)
__device__ __align__(16) float          g_H[N_NODES * OUT_DIM];
__device__ __align__(16) __nv_bfloat16  g_P[N_NODES * P_COLS];

// ---------------------------------------------------------------------------
// Kernel 1: H = F @ W + b   (fp32, tiled, BM=64 x BN=128, BK=16)
// ---------------------------------------------------------------------------
__global__ __launch_bounds__(256) void k1_proj(const float* __restrict__ F,
                                               const float* __restrict__ W,
                                               const float* __restrict__ b) {
    __shared__ float Fs[16][68];    // transposed: Fs[k][m]
    __shared__ float Ws[16][132];   // Ws[k][n]
    const int tid  = threadIdx.x;
    const int trow = tid >> 5;      // 0..7  (8 rows of 8)
    const int tcol = tid & 31;      // 0..31 (32 cols of 4)
    const int m0   = blockIdx.x * 64;

    float acc[8][4];
#pragma unroll
    for (int i = 0; i < 8; i++)
#pragma unroll
        for (int j = 0; j < 4; j++) acc[i][j] = 0.f;

    for (int kt = 0; kt < IN_DIM / 16; kt++) {
#pragma unroll
        for (int q = 0; q < 4; q++) {           // F tile 64x16 -> Fs[k][m]
            int f = tid + q * 256;
            int k = f & 15, m = f >> 4;
            Fs[k][m] = F[(m0 + m) * IN_DIM + kt * 16 + k];
        }
#pragma unroll
        for (int q = 0; q < 8; q++) {           // W tile 16x128 -> Ws[k][n]
            int f = tid + q * 256;
            int n = f & 127, k = f >> 7;
            Ws[k][n] = W[(kt * 16 + k) * OUT_DIM + n];
        }
        __syncthreads();
#pragma unroll
        for (int kk = 0; kk < 16; kk++) {
            float4 A0 = *(const float4*)&Fs[kk][trow * 8];
            float4 A1 = *(const float4*)&Fs[kk][trow * 8 + 4];
            float4 B0 = *(const float4*)&Ws[kk][tcol * 4];
            float av[8] = {A0.x, A0.y, A0.z, A0.w, A1.x, A1.y, A1.z, A1.w};
            float bv[4] = {B0.x, B0.y, B0.z, B0.w};
#pragma unroll
            for (int i = 0; i < 8; i++)
#pragma unroll
                for (int j = 0; j < 4; j++)
                    acc[i][j] = fmaf(av[i], bv[j], acc[i][j]);
        }
        __syncthreads();
    }
#pragma unroll
    for (int i = 0; i < 8; i++) {
        int r = m0 + trow * 8 + i;
#pragma unroll
        for (int j = 0; j < 4; j++) {
            int c = tcol * 4 + j;
            g_H[r * OUT_DIM + c] = acc[i][j] + b[c];
        }
    }
}

// ---------------------------------------------------------------------------
// Kernel 2: per row i: a2 = h·a2_w + a2_b, w = exp(a2),
//           P[i, 0:128] = bf16(w*h), P[i,128] = bf16(w), P[i,129:144] = 0
// One warp per row. (a1[i] is constant along the softmax row and cancels.)
// ---------------------------------------------------------------------------
__global__ __launch_bounds__(256) void k2_weights(const float* __restrict__ a2w,
                                                  const float* __restrict__ a2b) {
    const int tid  = threadIdx.x;
    const int lane = tid & 31;
    const int row  = blockIdx.x * 8 + (tid >> 5);
    const float* h = g_H + (size_t)row * OUT_DIM;

    float hv[4];
    float s = 0.f;
#pragma unroll
    for (int j = 0; j < 4; j++) {
        hv[j] = h[lane * 4 + j];
        s = fmaf(hv[j], a2w[lane * 4 + j], s);
    }
#pragma unroll
    for (int o = 16; o > 0; o >>= 1) s += __shfl_xor_sync(0xffffffffu, s, o);

    float w = expf(s + a2b[0]);

    __nv_bfloat16* p = g_P + (size_t)row * P_COLS;
#pragma unroll
    for (int j = 0; j < 4; j++) p[lane * 4 + j] = __float2bfloat16(w * hv[j]);
    if (lane < 16) p[128 + lane] = __float2bfloat16(lane == 0 ? w : 0.f);
}

// ---------------------------------------------------------------------------
// Kernel 3: C = adjBF16(8192x8192) @ P(8192x144); out = C[:, :128] / C[:,128]
// BM=64, BN=144 (full), BK=64. 128 CTAs, 256 threads (8 warps = 4M x 2N).
// adj int32 {0,1} -> bf16 via integer trick, double-buffered smem, mma.sync.
// ---------------------------------------------------------------------------
#define BM   64
#define BKK  64
#define ASTR 72    // 144B row stride: LDSM-conflict-free (36 words: r*4 mod 32)
#define BSTR 152   // 304B row stride: LDSM-conflict-free (76 words: r*12 mod 32)
#define SMEM_K3 (2 * BM * ASTR * 2 + 2 * BKK * BSTR * 2)  // 57344 bytes

#define MMA_OP(C, A0, A1, A2, A3, B0, B1)                                     \
    asm volatile(                                                             \
        "mma.sync.aligned.m16n8k16.row.col.f32.bf16.bf16.f32 "                \
        "{%0,%1,%2,%3},{%4,%5,%6,%7},{%8,%9},{%0,%1,%2,%3};"                  \
        : "+f"(C[0]), "+f"(C[1]), "+f"(C[2]), "+f"(C[3])                      \
        : "r"(A0), "r"(A1), "r"(A2), "r"(A3), "r"(B0), "r"(B1));

__global__ __launch_bounds__(256, 1) void k3_agg(const int* __restrict__ adj,
                                                 float* __restrict__ out) {
    extern __shared__ char sm[];
    __nv_bfloat16* Asm = (__nv_bfloat16*)sm;                       // [2][64][72]
    __nv_bfloat16* Bsm = (__nv_bfloat16*)(sm + 2 * BM * ASTR * 2); // [2][64][152]
    float* denSm = (float*)sm;  // reused after mainloop (A buf0 region)

    const int tid  = threadIdx.x;
    const int lane = tid & 31;
    const int warp = tid >> 5;
    const int wm   = warp & 3;   // M group: rows wm*16..+16
    const int wn   = warp >> 2;  // N group: cols wn*72..+72
    const int m0   = blockIdx.x * BM;

    const uint4* adjU4 = (const uint4*)adj;   // 2048 uint4 per adj row
    const uint4* pU4   = (const uint4*)g_P;   // 18 uint4 per P row (144 bf16)

    float acc[9][4];
#pragma unroll
    for (int t = 0; t < 9; t++)
#pragma unroll
        for (int j = 0; j < 4; j++) acc[t][j] = 0.f;

    uint4 aR[4], bR[5];

    auto loadAB = [&](int kIt) {
        const uint4* asrc = adjU4 + (size_t)m0 * 2048 + (size_t)kIt * 16;
#pragma unroll
        for (int q = 0; q < 4; q++) {
            int f = tid + q * 256;                    // 0..1023
            aR[q] = asrc[(size_t)(f >> 4) * 2048 + (f & 15)];
        }
        const uint4* bsrc = pU4 + (size_t)kIt * 64 * 18;  // tile is contiguous
#pragma unroll
        for (int q = 0; q < 5; q++) {
            int f = tid + q * 256;
            if (f < 1152) bR[q] = bsrc[f];
        }
    };

    auto storeAB = [&](int buf) {
        __nv_bfloat16* Ab = Asm + buf * (BM * ASTR);
#pragma unroll
        for (int q = 0; q < 4; q++) {
            int f = tid + q * 256;
            uint2 r;
            // {0,1} int32 pair -> packed bf16x2: (v0 | v1<<16) * 0x3F80
            r.x = (aR[q].x | (aR[q].y << 16)) * 0x3F80u;
            r.y = (aR[q].z | (aR[q].w << 16)) * 0x3F80u;
            *(uint2*)(Ab + (f >> 4) * ASTR + (f & 15) * 4) = r;
        }
        __nv_bfloat16* Bb = Bsm + buf * (BKK * BSTR);
#pragma unroll
        for (int q = 0; q < 5; q++) {
            int f = tid + q * 256;
            if (f < 1152)
                *(uint4*)(Bb + (f / 18) * BSTR + (f % 18) * 8) = bR[q];
        }
    };

    auto compute = [&](int buf) {
        const __nv_bfloat16* Ab = Asm + buf * (BM * ASTR) + wm * 16 * ASTR;
        const __nv_bfloat16* Bb = Bsm + buf * (BKK * BSTR) + wn * 72;
        unsigned aBase  = (unsigned)__cvta_generic_to_shared(
            Ab + (lane & 15) * ASTR + (lane >> 4) * 8);
        unsigned bBase  = (unsigned)__cvta_generic_to_shared(
            Bb + (lane & 15) * BSTR + (lane >> 4) * 8);
        unsigned b2Base = (unsigned)__cvta_generic_to_shared(
            Bb + (lane & 15) * BSTR + 64);
#pragma unroll
        for (int ks = 0; ks < 4; ks++) {
            unsigned a0, a1, a2, a3;
            asm volatile(
                "ldmatrix.sync.aligned.m8n8.x4.shared.b16 {%0,%1,%2,%3},[%4];"
                : "=r"(a0), "=r"(a1), "=r"(a2), "=r"(a3)
                : "r"(aBase + ks * 32));
#pragma unroll
            for (int p = 0; p < 4; p++) {
                unsigned b0, b1, b2, b3;
                asm volatile(
                    "ldmatrix.sync.aligned.m8n8.x4.trans.shared.b16 "
                    "{%0,%1,%2,%3},[%4];"
                    : "=r"(b0), "=r"(b1), "=r"(b2), "=r"(b3)
                    : "r"(bBase + ks * 16 * BSTR * 2 + p * 32));
                MMA_OP(acc[2 * p],     a0, a1, a2, a3, b0, b1);
                MMA_OP(acc[2 * p + 1], a0, a1, a2, a3, b2, b3);
            }
            unsigned b0, b1;
            asm volatile(
                "ldmatrix.sync.aligned.m8n8.x2.trans.shared.b16 {%0,%1},[%2];"
                : "=r"(b0), "=r"(b1)
                : "r"(b2Base + ks * 16 * BSTR * 2));
            MMA_OP(acc[8], a0, a1, a2, a3, b0, b1);
        }
    };

    // -------- mainloop: 128 K-iterations, 2-stage double buffer --------
    loadAB(0);
    storeAB(0);
    __syncthreads();
    for (int it = 0; it < 128; it++) {
        if (it + 1 < 128) loadAB(it + 1);   // LDGs in flight over compute
        compute(it & 1);
        if (it + 1 < 128) storeAB((it + 1) & 1);
        __syncthreads();
    }

    // -------- epilogue: out = num / den, den = C[:,128] --------
    __syncthreads();
    if (wn == 1 && (lane & 3) == 0) {       // col 128 = wn1, tile7, col0
        int r = wm * 16 + (lane >> 2);
        denSm[r]     = acc[7][0];
        denSm[r + 8] = acc[7][2];
    }
    __syncthreads();
    {
        int r = wm * 16 + (lane >> 2);
        float inv0 = 1.0f / denSm[r];
        float inv1 = 1.0f / denSm[r + 8];
#pragma unroll
        for (int t = 0; t < 9; t++) {
            int c = wn * 72 + t * 8 + (lane & 3) * 2;
            if (c < 128) {
                float* o0 = out + (size_t)(m0 + r) * 128 + c;
                float* o1 = out + (size_t)(m0 + r + 8) * 128 + c;
                o0[0] = acc[t][0] * inv0;
                o0[1] = acc[t][1] * inv0;
                o1[0] = acc[t][2] * inv1;
                o1[1] = acc[t][3] * inv1;
            }
        }
    }
}

// ---------------------------------------------------------------------------
extern "C" void kernel_launch(void* const* d_in, const int* in_sizes, int n_in,
                              void* d_out, int out_size) {
    const float* F   = (const float*)d_in[0];
    const int*   adj = (const int*)d_in[1];
    const float* W   = (const float*)d_in[2];
    const float* b   = (const float*)d_in[3];
    // d_in[4], d_in[5] (a1_w, a1_b) cancel in the row softmax — unused.
    const float* a2w = (const float*)d_in[6];
    const float* a2b = (const float*)d_in[7];
    float* out = (float*)d_out;

    k1_proj<<<128, 256>>>(F, W, b);
    k2_weights<<<1024, 256>>>(a2w, a2b);
    cudaFuncSetAttribute(k3_agg, cudaFuncAttributeMaxDynamicSharedMemorySize,
                         SMEM_K3);
    k3_agg<<<128, 256, SMEM_K3>>>(adj, out);
}

// round 9
// speedup vs baseline: 1.4093x; 1.4093x over previous
#include <cuda_runtime.h>
#include <cuda_bf16.h>

typedef unsigned int u32;
typedef unsigned long long u64;

#define N_NODES 8192
#define IN_DIM  256
#define OUT_DIM 128
#define PN      144      // 128 cols of w*h, col 128 = w, 129..143 = 0

#define BM3     128      // k3 M tile
#define KHALF   4096     // split-K = 2
#define NIT     64       // KHALF / 64
#define ASTR    72       // A smem row stride (elems): 144B, LDSM conflict-free
#define BSTR    152      // B smem row stride (elems): 304B, LDSM conflict-free
#define AST_E   (128 * ASTR)          // 9216 elems / A stage
#define BST_E   (64 * BSTR)           // 9728 elems / B stage
#define SM3     ((2 * AST_E + 3 * BST_E) * 2)   // 95232 B

// Scratch (device globals: no runtime allocation allowed)
__device__ __align__(16) __nv_bfloat16 g_P[N_NODES * PN];        // node-major
__device__ __align__(16) float         g_C[2 * N_NODES * PN];    // split-K partials

// ---------------------------------------------------------------------------
// Kernel 1 (fused proj + attention weights):
//   h = F@W + b (fp32); a2 = h.a2w + a2b; w = exp(a2)  [a1 cancels in softmax]
//   g_P[node][c] = bf16(w*h[c]) c<128; g_P[node][128] = bf16(w); 129..143 = 0
// BM=32 nodes/CTA -> 256 CTAs (R6 k1 was grid-limited at 128).
// ---------------------------------------------------------------------------
__global__ __launch_bounds__(256) void k1f(const float* __restrict__ F,
                                           const float* __restrict__ W,
                                           const float* __restrict__ b,
                                           const float* __restrict__ a2w,
                                           const float* __restrict__ a2b) {
    __shared__ float Fs[16][36];
    __shared__ float Ws[16][132];

    const int tid = threadIdx.x;
    const int tr  = tid >> 5;   // 0..7 -> nodes tr*4..+3
    const int tc  = tid & 31;   // 0..31 -> cols tc*4..+3
    const int m0  = blockIdx.x * 32;

    float acc[4][4];
#pragma unroll
    for (int i = 0; i < 4; i++)
#pragma unroll
        for (int j = 0; j < 4; j++) acc[i][j] = 0.f;

    for (int kt = 0; kt < IN_DIM / 16; kt++) {
#pragma unroll
        for (int q = 0; q < 2; q++) {
            int f = tid + q * 256;              // 0..511
            int m = f >> 4, k = f & 15;
            Fs[k][m] = F[(size_t)(m0 + m) * IN_DIM + kt * 16 + k];
        }
#pragma unroll
        for (int q = 0; q < 8; q++) {
            int f = tid + q * 256;              // 0..2047
            int n = f & 127, k = f >> 7;
            Ws[k][n] = W[(size_t)(kt * 16 + k) * OUT_DIM + n];
        }
        __syncthreads();
#pragma unroll
        for (int kk = 0; kk < 16; kk++) {
            float4 av = *(const float4*)&Fs[kk][tr * 4];
            float4 bv = *(const float4*)&Ws[kk][tc * 4];
            float a[4] = {av.x, av.y, av.z, av.w};
            float c[4] = {bv.x, bv.y, bv.z, bv.w};
#pragma unroll
            for (int i = 0; i < 4; i++)
#pragma unroll
                for (int j = 0; j < 4; j++)
                    acc[i][j] = fmaf(a[i], c[j], acc[i][j]);
        }
        __syncthreads();
    }

    float4 bb = *(const float4*)&b[tc * 4];
    float4 aw = *(const float4*)&a2w[tc * 4];
    float a2b0 = a2b[0];
    float bias[4] = {bb.x, bb.y, bb.z, bb.w};
    float awv[4]  = {aw.x, aw.y, aw.z, aw.w};

#pragma unroll
    for (int i = 0; i < 4; i++) {
        float h[4];
        float s = 0.f;
#pragma unroll
        for (int j = 0; j < 4; j++) {
            h[j] = acc[i][j] + bias[j];
            s = fmaf(h[j], awv[j], s);
        }
#pragma unroll
        for (int o = 16; o > 0; o >>= 1) s += __shfl_xor_sync(0xffffffffu, s, o);
        float wv = expf(s + a2b0);

        __nv_bfloat16* p = g_P + (size_t)(m0 + tr * 4 + i) * PN;
#pragma unroll
        for (int j = 0; j < 4; j++)
            p[tc * 4 + j] = __float2bfloat16(wv * h[j]);
        if (tc < 16) p[128 + tc] = __float2bfloat16(tc == 0 ? wv : 0.f);
    }
}

// ---------------------------------------------------------------------------
// Kernel 3: Cpart[ks] = adjBF16[m0:+128, K-half] @ P  via mma.sync bf16.
// 64 Mtiles x 2 Ksplits = 128 CTAs, 256 thr (8 warps: WM=4 x WN=2).
// A: LDG int32 -> 2-IMAD pack -> STS (2-stage). B: cp.async (3-stage).
// One __syncthreads per K-iteration.
// ---------------------------------------------------------------------------
#define MMA_OP(C, A0, A1, A2, A3, B0, B1)                                     \
    asm volatile(                                                             \
        "mma.sync.aligned.m16n8k16.row.col.f32.bf16.bf16.f32 "                \
        "{%0,%1,%2,%3},{%4,%5,%6,%7},{%8,%9},{%0,%1,%2,%3};"                  \
        : "+f"(C[0]), "+f"(C[1]), "+f"(C[2]), "+f"(C[3])                      \
        : "r"(A0), "r"(A1), "r"(A2), "r"(A3), "r"(B0), "r"(B1));

__global__ __launch_bounds__(256, 1) void k3_agg(const int* __restrict__ adj) {
    extern __shared__ __nv_bfloat16 smem[];
    __nv_bfloat16* Asm = smem;                  // 2 stages x [128][ASTR]
    __nv_bfloat16* Bsm = smem + 2 * AST_E;      // 3 stages x [64][BSTR]

    const int tid  = threadIdx.x;
    const int lane = tid & 31;
    const int warp = tid >> 5;
    const int wm   = warp & 3;    // rows wm*32 .. +32 (2 m16 tiles)
    const int wn   = warp >> 2;   // cols wn*72 .. +72 (9 n8 tiles)
    const int ks   = blockIdx.x & 1;
    const int m0   = (blockIdx.x >> 1) * BM3;

    const uint4* adjU4 = (const uint4*)adj;     // 2048 uint4 per adj row
    const size_t kbU4  = (size_t)ks * (KHALF / 4);

    u32 smbB;
    {
        u64 t = (u64)__cvta_generic_to_shared(Bsm);
        smbB = (u32)t;
    }

    float acc[2][9][4];
#pragma unroll
    for (int mt = 0; mt < 2; mt++)
#pragma unroll
        for (int nt = 0; nt < 9; nt++)
#pragma unroll
            for (int j = 0; j < 4; j++) acc[mt][nt][j] = 0.f;

    uint4 aR[8];

    auto ldgA = [&](int it) {
#pragma unroll
        for (int q = 0; q < 8; q++) {
            int f = tid + q * 256;                       // 0..2047
            aR[q] = adjU4[(size_t)(m0 + (f >> 4)) * 2048 + kbU4 +
                          (size_t)it * 16 + (f & 15)];
        }
    };
    auto stsA = [&](int buf) {
        __nv_bfloat16* Ab = Asm + buf * AST_E;
#pragma unroll
        for (int q = 0; q < 8; q++) {
            int f = tid + q * 256;
            uint2 r;
            // {0,1} int32 pair -> packed bf16x2: (hi*65536+lo) * 0x3F80
            r.x = (aR[q].y * 65536u + aR[q].x) * 0x3F80u;
            r.y = (aR[q].w * 65536u + aR[q].z) * 0x3F80u;
            *(uint2*)(Ab + (f >> 4) * ASTR + (f & 15) * 4) = r;
        }
    };
    auto cpB = [&](int it, int s) {
        u32 bb = smbB + s * BST_E * 2;
#pragma unroll
        for (int q = 0; q < 5; q++) {
            int f = tid + q * 256;                       // need f < 1152
            if (f < 1152) {
                int r = f / 18, c = f % 18;
                const __nv_bfloat16* src =
                    g_P + (size_t)(ks * KHALF + it * 64 + r) * PN + c * 8;
                asm volatile("cp.async.cg.shared.global [%0], [%1], 16;"
                             :: "r"(bb + (u32)r * (BSTR * 2) + (u32)c * 16),
                                "l"(src) : "memory");
            }
        }
        asm volatile("cp.async.commit_group;" ::: "memory");
    };
    auto compute = [&](int abuf, int bst) {
        const __nv_bfloat16* Ab = Asm + abuf * AST_E + wm * 32 * ASTR;
        const __nv_bfloat16* Bb = Bsm + bst * BST_E + wn * 72;
        u32 aB = (u32)__cvta_generic_to_shared(
            Ab + (lane & 15) * ASTR + (lane >> 4) * 8);
        u32 bB = (u32)__cvta_generic_to_shared(
            Bb + (lane & 15) * BSTR + (lane >> 4) * 8);
        u32 b2 = (u32)__cvta_generic_to_shared(
            Bb + (lane & 15) * BSTR + 64);
#pragma unroll
        for (int k2 = 0; k2 < 4; k2++) {
            u32 a[2][4];
#pragma unroll
            for (int mt = 0; mt < 2; mt++)
                asm volatile(
                    "ldmatrix.sync.aligned.m8n8.x4.shared.b16 "
                    "{%0,%1,%2,%3},[%4];"
                    : "=r"(a[mt][0]), "=r"(a[mt][1]), "=r"(a[mt][2]),
                      "=r"(a[mt][3])
                    : "r"(aB + mt * 16 * ASTR * 2 + k2 * 32));
            u32 bfr[9][2];
#pragma unroll
            for (int p = 0; p < 4; p++)
                asm volatile(
                    "ldmatrix.sync.aligned.m8n8.x4.trans.shared.b16 "
                    "{%0,%1,%2,%3},[%4];"
                    : "=r"(bfr[2 * p][0]), "=r"(bfr[2 * p][1]),
                      "=r"(bfr[2 * p + 1][0]), "=r"(bfr[2 * p + 1][1])
                    : "r"(bB + k2 * 16 * BSTR * 2 + p * 32));
            asm volatile(
                "ldmatrix.sync.aligned.m8n8.x2.trans.shared.b16 {%0,%1},[%2];"
                : "=r"(bfr[8][0]), "=r"(bfr[8][1])
                : "r"(b2 + k2 * 16 * BSTR * 2));
#pragma unroll
            for (int mt = 0; mt < 2; mt++)
#pragma unroll
                for (int nt = 0; nt < 9; nt++)
                    MMA_OP(acc[mt][nt], a[mt][0], a[mt][1], a[mt][2], a[mt][3],
                           bfr[nt][0], bfr[nt][1]);
        }
    };

    // -------- prologue --------
    cpB(0, 0);
    cpB(1, 1);
    ldgA(0);
    stsA(0);
    ldgA(1);

    // -------- mainloop --------
#pragma unroll 1
    for (int it = 0; it < NIT; it++) {
        if (it < NIT - 1)
            asm volatile("cp.async.wait_group 1;" ::: "memory");
        else
            asm volatile("cp.async.wait_group 0;" ::: "memory");
        __syncthreads();                         // tile(it) A+B visible
        if (it + 2 < NIT) cpB(it + 2, (it + 2) % 3);
        compute(it & 1, it % 3);
        if (it + 1 < NIT) stsA((it + 1) & 1);    // aR holds tile it+1
        if (it + 2 < NIT) ldgA(it + 2);
    }

    // -------- epilogue: write split-K partials --------
    float* dstB = g_C + (size_t)ks * N_NODES * PN;
#pragma unroll
    for (int mt = 0; mt < 2; mt++) {
        int r0 = m0 + wm * 32 + mt * 16 + (lane >> 2);
#pragma unroll
        for (int nt = 0; nt < 9; nt++) {
            int c = wn * 72 + nt * 8 + (lane & 3) * 2;
            float* d0 = dstB + (size_t)r0 * PN + c;
            float* d1 = dstB + (size_t)(r0 + 8) * PN + c;
            d0[0] = acc[mt][nt][0];
            d0[1] = acc[mt][nt][1];
            d1[0] = acc[mt][nt][2];
            d1[1] = acc[mt][nt][3];
        }
    }
}

// ---------------------------------------------------------------------------
// Kernel 4: out = (C0 + C1)[:, :128] / (C0 + C1)[:, 128]
// ---------------------------------------------------------------------------
__global__ __launch_bounds__(256) void k4_div(float* __restrict__ out) {
    const int tid  = threadIdx.x;
    const int row  = blockIdx.x * 8 + (tid >> 5);
    const int lane = tid & 31;
    const float* c0 = g_C + (size_t)row * PN;
    const float* c1 = g_C + (size_t)(N_NODES + row) * PN;
    float4 v0 = *(const float4*)(c0 + lane * 4);
    float4 v1 = *(const float4*)(c1 + lane * 4);
    float inv = 1.0f / (c0[128] + c1[128]);
    float4 r;
    r.x = (v0.x + v1.x) * inv;
    r.y = (v0.y + v1.y) * inv;
    r.z = (v0.z + v1.z) * inv;
    r.w = (v0.w + v1.w) * inv;
    *(float4*)(out + (size_t)row * OUT_DIM + lane * 4) = r;
}

// ---------------------------------------------------------------------------
extern "C" void kernel_launch(void* const* d_in, const int* in_sizes, int n_in,
                              void* d_out, int out_size) {
    const float* F   = (const float*)d_in[0];
    const int*   adj = (const int*)d_in[1];
    const float* W   = (const float*)d_in[2];
    const float* b   = (const float*)d_in[3];
    // d_in[4], d_in[5] (a1_w, a1_b) cancel in the row softmax — unused.
    const float* a2w = (const float*)d_in[6];
    const float* a2b = (const float*)d_in[7];
    float* out = (float*)d_out;

    k1f<<<256, 256>>>(F, W, b, a2w, a2b);
    cudaFuncSetAttribute(k3_agg, cudaFuncAttributeMaxDynamicSharedMemorySize,
                         SM3);
    k3_agg<<<128, 256, SM3>>>(adj);
    k4_div<<<1024, 256>>>(out);
}

// round 11
// speedup vs baseline: 1.5925x; 1.1300x over previous
#include <cuda_runtime.h>
#include <cuda_bf16.h>

typedef unsigned int u32;
typedef unsigned long long u64;

#define N_NODES 8192
#define IN_DIM  256
#define OUT_DIM 128
#define PN      144      // 128 cols of w*h, col 128 = w, 129..143 = 0

#define BM3     128      // k3 M tile
#define KHALF   4096     // split-K = 2
#define NIT     64       // KHALF / 64
#define ASTR    72       // A smem row stride (elems): 144B, LDSM conflict-free
#define BSTR    152      // B smem row stride (elems): 304B, LDSM conflict-free
#define AST_E   (128 * ASTR)          // elems / A stage
#define BST_E   (64 * BSTR)           // elems / B stage
#define SM3     ((2 * AST_E + 4 * BST_E) * 2)   // 114688 B

// Scratch (device globals: no runtime allocation allowed)
__device__ __align__(16) __nv_bfloat16 g_P[N_NODES * PN];        // node-major
__device__ __align__(16) float         g_C[2 * N_NODES * PN];    // split-K partials

#define MMA_OP(C, A0, A1, A2, A3, B0, B1)                                     \
    asm volatile(                                                             \
        "mma.sync.aligned.m16n8k16.row.col.f32.bf16.bf16.f32 "                \
        "{%0,%1,%2,%3},{%4,%5,%6,%7},{%8,%9},{%0,%1,%2,%3};"                  \
        : "+f"(C[0]), "+f"(C[1]), "+f"(C[2]), "+f"(C[3])                      \
        : "r"(A0), "r"(A1), "r"(A2), "r"(A3), "r"(B0), "r"(B1));

#define LDSM_X4(R0, R1, R2, R3, ADDR)                                         \
    asm volatile("ldmatrix.sync.aligned.m8n8.x4.shared.b16 {%0,%1,%2,%3},[%4];" \
                 : "=r"(R0), "=r"(R1), "=r"(R2), "=r"(R3) : "r"(ADDR));

#define LDSM_X4T(R0, R1, R2, R3, ADDR)                                        \
    asm volatile("ldmatrix.sync.aligned.m8n8.x4.trans.shared.b16 "            \
                 "{%0,%1,%2,%3},[%4];"                                        \
                 : "=r"(R0), "=r"(R1), "=r"(R2), "=r"(R3) : "r"(ADDR));

// ---------------------------------------------------------------------------
// Kernel 1 (fused proj + weights, TENSOR CORE, bf16-split 3-pass fp32-grade):
//   h = F@W + b; a2 = h.a2w + a2b; w = exp(a2)  [a1 cancels in row softmax]
//   g_P[node][c] = bf16(w*h[c]) c<128; g_P[node][128] = bf16(w); 129..143 = 0
// BM=32 nodes/CTA -> 256 CTAs; 8 warps = WM2 x WN4, warp tile 16m x 32n.
// ---------------------------------------------------------------------------
#define K1_ASTR 72     // 144B rows, LDSM conflict-free
#define K1_BSTR 136    // 272B rows (68w = 4 mod 32), LDSM conflict-free

__global__ __launch_bounds__(256) void k1t(const float* __restrict__ F,
                                           const float* __restrict__ W,
                                           const float* __restrict__ b,
                                           const float* __restrict__ a2w,
                                           const float* __restrict__ a2b) {
    __shared__ __nv_bfloat16 Ah[32][K1_ASTR], Al[32][K1_ASTR];
    __shared__ __nv_bfloat16 Wh[64][K1_BSTR], Wl[64][K1_BSTR];
    __shared__ float red[32][4];
    __shared__ float wrow[32];

    const int tid  = threadIdx.x;
    const int lane = tid & 31;
    const int warp = tid >> 5;
    const int wm   = warp & 1;    // rows wm*16 .. +16
    const int wn   = warp >> 1;   // cols wn*32 .. +32 (4 n8-tiles)
    const int m0   = blockIdx.x * 32;

    float acc[4][4];
#pragma unroll
    for (int nt = 0; nt < 4; nt++)
#pragma unroll
        for (int j = 0; j < 4; j++) acc[nt][j] = 0.f;

    for (int kt = 0; kt < 4; kt++) {
        // F chunk 32x64 fp32 -> Ah/Al (hi/lo bf16 split)
#pragma unroll
        for (int q = 0; q < 2; q++) {
            int f = tid + q * 256;              // 0..511
            int m = f >> 4, k4 = (f & 15) * 4;
            float4 v = *(const float4*)&F[(size_t)(m0 + m) * IN_DIM +
                                          kt * 64 + k4];
            float vv[4] = {v.x, v.y, v.z, v.w};
#pragma unroll
            for (int j = 0; j < 4; j++) {
                __nv_bfloat16 hi = __float2bfloat16(vv[j]);
                Ah[m][k4 + j] = hi;
                Al[m][k4 + j] = __float2bfloat16(vv[j] - __bfloat162float(hi));
            }
        }
        // W chunk 64x128 fp32 -> Wh/Wl
#pragma unroll
        for (int q = 0; q < 8; q++) {
            int f = tid + q * 256;              // 0..2047
            int k = f >> 5, n4 = (f & 31) * 4;
            float4 v = *(const float4*)&W[(size_t)(kt * 64 + k) * OUT_DIM + n4];
            float vv[4] = {v.x, v.y, v.z, v.w};
#pragma unroll
            for (int j = 0; j < 4; j++) {
                __nv_bfloat16 hi = __float2bfloat16(vv[j]);
                Wh[k][n4 + j] = hi;
                Wl[k][n4 + j] = __float2bfloat16(vv[j] - __bfloat162float(hi));
            }
        }
        __syncthreads();

        u32 aH = (u32)__cvta_generic_to_shared(
            &Ah[wm * 16 + (lane & 15)][(lane >> 4) * 8]);
        u32 aL = (u32)__cvta_generic_to_shared(
            &Al[wm * 16 + (lane & 15)][(lane >> 4) * 8]);
        u32 bH = (u32)__cvta_generic_to_shared(
            &Wh[lane & 15][wn * 32 + (lane >> 4) * 8]);
        u32 bL = (u32)__cvta_generic_to_shared(
            &Wl[lane & 15][wn * 32 + (lane >> 4) * 8]);

#pragma unroll
        for (int k2 = 0; k2 < 4; k2++) {
            u32 ah[4], al[4], wh[4][2], wl[4][2];
            LDSM_X4(ah[0], ah[1], ah[2], ah[3], aH + k2 * 32);
            LDSM_X4(al[0], al[1], al[2], al[3], aL + k2 * 32);
#pragma unroll
            for (int p = 0; p < 2; p++) {
                LDSM_X4T(wh[2 * p][0], wh[2 * p][1], wh[2 * p + 1][0],
                         wh[2 * p + 1][1],
                         bH + k2 * 16 * (K1_BSTR * 2) + p * 32);
                LDSM_X4T(wl[2 * p][0], wl[2 * p][1], wl[2 * p + 1][0],
                         wl[2 * p + 1][1],
                         bL + k2 * 16 * (K1_BSTR * 2) + p * 32);
            }
#pragma unroll
            for (int nt = 0; nt < 4; nt++) {
                MMA_OP(acc[nt], ah[0], ah[1], ah[2], ah[3], wh[nt][0],
                       wh[nt][1]);
                MMA_OP(acc[nt], ah[0], ah[1], ah[2], ah[3], wl[nt][0],
                       wl[nt][1]);
                MMA_OP(acc[nt], al[0], al[1], al[2], al[3], wh[nt][0],
                       wh[nt][1]);
            }
        }
        __syncthreads();
    }

    // ---- epilogue: bias, a2 dot, exp, scale, store bf16 ----
    const int r0l = wm * 16 + (lane >> 2);   // local rows
    const int r1l = r0l + 8;
    float hreg[4][4];
    float p0 = 0.f, p1 = 0.f;
#pragma unroll
    for (int nt = 0; nt < 4; nt++) {
        int c = wn * 32 + nt * 8 + (lane & 3) * 2;
        float2 bb = *(const float2*)&b[c];
        float2 aw = *(const float2*)&a2w[c];
        hreg[nt][0] = acc[nt][0] + bb.x;
        hreg[nt][1] = acc[nt][1] + bb.y;
        hreg[nt][2] = acc[nt][2] + bb.x;
        hreg[nt][3] = acc[nt][3] + bb.y;
        p0 = fmaf(hreg[nt][0], aw.x, fmaf(hreg[nt][1], aw.y, p0));
        p1 = fmaf(hreg[nt][2], aw.x, fmaf(hreg[nt][3], aw.y, p1));
    }
    p0 += __shfl_xor_sync(0xffffffffu, p0, 1);
    p0 += __shfl_xor_sync(0xffffffffu, p0, 2);
    p1 += __shfl_xor_sync(0xffffffffu, p1, 1);
    p1 += __shfl_xor_sync(0xffffffffu, p1, 2);
    if ((lane & 3) == 0) {
        red[r0l][wn] = p0;
        red[r1l][wn] = p1;
    }
    __syncthreads();
    if (tid < 32) {
        float s = red[tid][0] + red[tid][1] + red[tid][2] + red[tid][3] +
                  a2b[0];
        float wv = expf(s);
        wrow[tid] = wv;
        g_P[(size_t)(m0 + tid) * PN + 128] = __float2bfloat16(wv);
    }
    // zero cols 129..143
#pragma unroll
    for (int q = 0; q < 2; q++) {
        int j = tid + q * 256;                  // 0..511
        int r = j >> 4, c = j & 15;
        if (c > 0)
            g_P[(size_t)(m0 + r) * PN + 128 + c] = __float2bfloat16(0.f);
    }
    __syncthreads();
    {
        float w0 = wrow[r0l], w1 = wrow[r1l];
#pragma unroll
        for (int nt = 0; nt < 4; nt++) {
            int c = wn * 32 + nt * 8 + (lane & 3) * 2;
            *(__nv_bfloat162*)(g_P + (size_t)(m0 + r0l) * PN + c) =
                __floats2bfloat162_rn(w0 * hreg[nt][0], w0 * hreg[nt][1]);
            *(__nv_bfloat162*)(g_P + (size_t)(m0 + r1l) * PN + c) =
                __floats2bfloat162_rn(w1 * hreg[nt][2], w1 * hreg[nt][3]);
        }
    }
}

// ---------------------------------------------------------------------------
// Kernel 3: Cpart[ks] = adjBF16[m0:+128, K-half] @ P  via mma.sync bf16.
// 64 Mtiles x 2 Ksplits = 128 CTAs, 256 thr (8 warps: WM=4 x WN=2).
// A: LDG int32 -> 2-IMAD pack -> STS (2-stage regs+smem).
// B: cp.async, 4-stage, prefetch distance 3, wait_group 2.
// ---------------------------------------------------------------------------
__global__ __launch_bounds__(256, 1) void k3_agg(const int* __restrict__ adj) {
    extern __shared__ __nv_bfloat16 smem[];
    __nv_bfloat16* Asm = smem;                  // 2 stages x [128][ASTR]
    __nv_bfloat16* Bsm = smem + 2 * AST_E;      // 4 stages x [64][BSTR]

    const int tid  = threadIdx.x;
    const int lane = tid & 31;
    const int warp = tid >> 5;
    const int wm   = warp & 3;    // rows wm*32 .. +32 (2 m16 tiles)
    const int wn   = warp >> 2;   // cols wn*72 .. +72 (9 n8 tiles)
    const int ks   = blockIdx.x & 1;
    const int m0   = (blockIdx.x >> 1) * BM3;

    const uint4* adjU4 = (const uint4*)adj;     // 2048 uint4 per adj row
    const size_t kbU4  = (size_t)ks * (KHALF / 4);

    u32 smbB = (u32)__cvta_generic_to_shared(Bsm);

    float acc[2][9][4];
#pragma unroll
    for (int mt = 0; mt < 2; mt++)
#pragma unroll
        for (int nt = 0; nt < 9; nt++)
#pragma unroll
            for (int j = 0; j < 4; j++) acc[mt][nt][j] = 0.f;

    uint4 aR[8];

    auto ldgA = [&](int it) {
#pragma unroll
        for (int q = 0; q < 8; q++) {
            int f = tid + q * 256;                       // 0..2047
            aR[q] = adjU4[(size_t)(m0 + (f >> 4)) * 2048 + kbU4 +
                          (size_t)it * 16 + (f & 15)];
        }
    };
    auto stsA = [&](int buf) {
        __nv_bfloat16* Ab = Asm + buf * AST_E;
#pragma unroll
        for (int q = 0; q < 8; q++) {
            int f = tid + q * 256;
            uint2 r;
            // {0,1} int32 pair -> packed bf16x2: (hi*65536+lo) * 0x3F80
            r.x = (aR[q].y * 65536u + aR[q].x) * 0x3F80u;
            r.y = (aR[q].w * 65536u + aR[q].z) * 0x3F80u;
            *(uint2*)(Ab + (f >> 4) * ASTR + (f & 15) * 4) = r;
        }
    };
    auto cpB = [&](int it, int s) {
        u32 bb = smbB + s * BST_E * 2;
#pragma unroll
        for (int q = 0; q < 5; q++) {
            int f = tid + q * 256;                       // need f < 1152
            if (f < 1152) {
                int r = f / 18, c = f % 18;
                const __nv_bfloat16* src =
                    g_P + (size_t)(ks * KHALF + it * 64 + r) * PN + c * 8;
                asm volatile("cp.async.cg.shared.global [%0], [%1], 16;"
                             :: "r"(bb + (u32)r * (BSTR * 2) + (u32)c * 16),
                                "l"(src) : "memory");
            }
        }
        asm volatile("cp.async.commit_group;" ::: "memory");
    };
    auto compute = [&](int abuf, int bst) {
        const __nv_bfloat16* Ab = Asm + abuf * AST_E + wm * 32 * ASTR;
        const __nv_bfloat16* Bb = Bsm + bst * BST_E + wn * 72;
        u32 aB = (u32)__cvta_generic_to_shared(
            Ab + (lane & 15) * ASTR + (lane >> 4) * 8);
        u32 bB = (u32)__cvta_generic_to_shared(
            Bb + (lane & 15) * BSTR + (lane >> 4) * 8);
        u32 b2 = (u32)__cvta_generic_to_shared(
            Bb + (lane & 15) * BSTR + 64);
#pragma unroll
        for (int k2 = 0; k2 < 4; k2++) {
            u32 a[2][4];
#pragma unroll
            for (int mt = 0; mt < 2; mt++)
                LDSM_X4(a[mt][0], a[mt][1], a[mt][2], a[mt][3],
                        aB + mt * 16 * (ASTR * 2) + k2 * 32);
            u32 bfr[9][2];
#pragma unroll
            for (int p = 0; p < 4; p++)
                LDSM_X4T(bfr[2 * p][0], bfr[2 * p][1], bfr[2 * p + 1][0],
                         bfr[2 * p + 1][1],
                         bB + k2 * 16 * (BSTR * 2) + p * 32);
            asm volatile(
                "ldmatrix.sync.aligned.m8n8.x2.trans.shared.b16 {%0,%1},[%2];"
                : "=r"(bfr[8][0]), "=r"(bfr[8][1])
                : "r"(b2 + k2 * 16 * (BSTR * 2)));
#pragma unroll
            for (int mt = 0; mt < 2; mt++)
#pragma unroll
                for (int nt = 0; nt < 9; nt++)
                    MMA_OP(acc[mt][nt], a[mt][0], a[mt][1], a[mt][2], a[mt][3],
                           bfr[nt][0], bfr[nt][1]);
        }
    };

    // -------- prologue --------
    cpB(0, 0);
    cpB(1, 1);
    cpB(2, 2);
    ldgA(0);
    stsA(0);
    ldgA(1);

    // -------- mainloop --------
#pragma unroll 1
    for (int it = 0; it < NIT; it++) {
        if (it <= NIT - 3)
            asm volatile("cp.async.wait_group 2;" ::: "memory");
        else if (it == NIT - 2)
            asm volatile("cp.async.wait_group 1;" ::: "memory");
        else
            asm volatile("cp.async.wait_group 0;" ::: "memory");
        __syncthreads();                         // tile(it) A+B visible
        if (it + 3 < NIT) cpB(it + 3, (it + 3) & 3);
        compute(it & 1, it & 3);
        if (it + 1 < NIT) stsA((it + 1) & 1);    // aR holds tile it+1
        if (it + 2 < NIT) ldgA(it + 2);
    }

    // -------- epilogue: write split-K partials --------
    float* dstB = g_C + (size_t)ks * N_NODES * PN;
#pragma unroll
    for (int mt = 0; mt < 2; mt++) {
        int r0 = m0 + wm * 32 + mt * 16 + (lane >> 2);
#pragma unroll
        for (int nt = 0; nt < 9; nt++) {
            int c = wn * 72 + nt * 8 + (lane & 3) * 2;
            float* d0 = dstB + (size_t)r0 * PN + c;
            float* d1 = dstB + (size_t)(r0 + 8) * PN + c;
            d0[0] = acc[mt][nt][0];
            d0[1] = acc[mt][nt][1];
            d1[0] = acc[mt][nt][2];
            d1[1] = acc[mt][nt][3];
        }
    }
}

// ---------------------------------------------------------------------------
// Kernel 4: out = (C0 + C1)[:, :128] / (C0 + C1)[:, 128]
// ---------------------------------------------------------------------------
__global__ __launch_bounds__(256) void k4_div(float* __restrict__ out) {
    const int tid  = threadIdx.x;
    const int row  = blockIdx.x * 8 + (tid >> 5);
    const int lane = tid & 31;
    const float* c0 = g_C + (size_t)row * PN;
    const float* c1 = g_C + (size_t)(N_NODES + row) * PN;
    float4 v0 = *(const float4*)(c0 + lane * 4);
    float4 v1 = *(const float4*)(c1 + lane * 4);
    float inv = 1.0f / (c0[128] + c1[128]);
    float4 r;
    r.x = (v0.x + v1.x) * inv;
    r.y = (v0.y + v1.y) * inv;
    r.z = (v0.z + v1.z) * inv;
    r.w = (v0.w + v1.w) * inv;
    *(float4*)(out + (size_t)row * OUT_DIM + lane * 4) = r;
}

// ---------------------------------------------------------------------------
extern "C" void kernel_launch(void* const* d_in, const int* in_sizes, int n_in,
                              void* d_out, int out_size) {
    const float* F   = (const float*)d_in[0];
    const int*   adj = (const int*)d_in[1];
    const float* W   = (const float*)d_in[2];
    const float* b   = (const float*)d_in[3];
    // d_in[4], d_in[5] (a1_w, a1_b) cancel in the row softmax — unused.
    const float* a2w = (const float*)d_in[6];
    const float* a2b = (const float*)d_in[7];
    float* out = (float*)d_out;

    k1t<<<256, 256>>>(F, W, b, a2w, a2b);
    cudaFuncSetAttribute(k3_agg, cudaFuncAttributeMaxDynamicSharedMemorySize,
                         SM3);
    k3_agg<<<128, 256, SM3>>>(adj);
    k4_div<<<1024, 256>>>(out);
}

// round 16
// speedup vs baseline: 1.5983x; 1.0037x over previous
#include <cuda_runtime.h>
#include <cuda_bf16.h>

typedef unsigned int u32;
typedef unsigned long long u64;

#define N_NODES 8192
#define IN_DIM  256
#define OUT_DIM 128
#define PN      144      // g_P row stride; cols: 0..127 w*h, 128 w, 129..135 0

#define BM3     128      // k3 M tile
#define KHALF   4096     // split-K = 2
#define NIT     64       // KHALF / 64
#define ASTR    72       // A smem row stride: 144B (16B-mult), LDSM conflict-free
#define BSTR    136      // B smem row stride: 272B = 17*16 (aligned!), 68w -> r*4 mod 32 distinct
#define BN3     136      // N tile: 128 out cols + den col + 7 zero pad
#define AST_E   (128 * ASTR)
#define BST_E   (64 * BSTR)
#define SM3     ((2 * AST_E + 4 * BST_E) * 2)   // 106496 B

// Scratch (device globals: no runtime allocation allowed)
__device__ __align__(16) __nv_bfloat16 g_P[N_NODES * PN];        // node-major
__device__ __align__(16) float         g_C[2 * N_NODES * PN];    // split-K partials

#define MMA_OP(C, A0, A1, A2, A3, B0, B1)                                     \
    asm volatile(                                                             \
        "mma.sync.aligned.m16n8k16.row.col.f32.bf16.bf16.f32 "                \
        "{%0,%1,%2,%3},{%4,%5,%6,%7},{%8,%9},{%0,%1,%2,%3};"                  \
        : "+f"(C[0]), "+f"(C[1]), "+f"(C[2]), "+f"(C[3])                      \
        : "r"(A0), "r"(A1), "r"(A2), "r"(A3), "r"(B0), "r"(B1));

#define LDSM_X4(R0, R1, R2, R3, ADDR)                                         \
    asm volatile("ldmatrix.sync.aligned.m8n8.x4.shared.b16 {%0,%1,%2,%3},[%4];" \
                 : "=r"(R0), "=r"(R1), "=r"(R2), "=r"(R3) : "r"(ADDR));

#define LDSM_X4T(R0, R1, R2, R3, ADDR)                                        \
    asm volatile("ldmatrix.sync.aligned.m8n8.x4.trans.shared.b16 "            \
                 "{%0,%1,%2,%3},[%4];"                                        \
                 : "=r"(R0), "=r"(R1), "=r"(R2), "=r"(R3) : "r"(ADDR));

// ---------------------------------------------------------------------------
// Kernel 1: fused proj + weights, tensor-core bf16-split 3-pass.
// BM=64 -> 128 CTAs = exactly one wave. 8 warps = WM2 x WN4.
//   h = F@W + b; w = exp(h.a2w + a2b)   [a1 cancels in the row softmax]
//   g_P[node][c] = bf16(w*h[c]) c<128; [128] = bf16(w); [129..135] = 0
// ---------------------------------------------------------------------------
#define K1_ASTR 72     // 144B rows
#define K1_WSTR 136    // 272B rows (68w -> r*4 mod 32 distinct)
#define K1_AE   (64 * K1_ASTR)      // 4608
#define K1_WE   (64 * K1_WSTR)      // 8704
#define K1_SMEM (2 * (K1_AE + K1_WE) * 2 + 64 * 4 * 4 + 64 * 4)  // 54528 B

__global__ __launch_bounds__(256) void k1t(const float* __restrict__ F,
                                           const float* __restrict__ W,
                                           const float* __restrict__ b,
                                           const float* __restrict__ a2w,
                                           const float* __restrict__ a2b) {
    extern __shared__ __nv_bfloat16 k1s[];
    __nv_bfloat16* Ah = k1s;
    __nv_bfloat16* Al = k1s + K1_AE;
    __nv_bfloat16* Wh = k1s + 2 * K1_AE;
    __nv_bfloat16* Wl = k1s + 2 * K1_AE + K1_WE;
    float* red  = (float*)(k1s + 2 * (K1_AE + K1_WE));   // [64][4]
    float* wrow = red + 256;                             // [64]

    const int tid  = threadIdx.x;
    const int lane = tid & 31;
    const int warp = tid >> 5;
    const int wm   = warp & 1;    // rows wm*32..+32 (2 m16 tiles)
    const int wn   = warp >> 1;   // cols wn*32..+32 (4 n8 tiles)
    const int m0   = blockIdx.x * 64;

    float acc[2][4][4];
#pragma unroll
    for (int mt = 0; mt < 2; mt++)
#pragma unroll
        for (int nt = 0; nt < 4; nt++)
#pragma unroll
            for (int j = 0; j < 4; j++) acc[mt][nt][j] = 0.f;

    for (int kt = 0; kt < 4; kt++) {
        // F chunk 64x64 fp32 -> hi/lo bf16 split
#pragma unroll
        for (int q = 0; q < 4; q++) {
            int f = tid + q * 256;              // 0..1023
            int m = f >> 4, k4 = (f & 15) * 4;
            float4 v = *(const float4*)&F[(size_t)(m0 + m) * IN_DIM +
                                          kt * 64 + k4];
            float vv[4] = {v.x, v.y, v.z, v.w};
#pragma unroll
            for (int j = 0; j < 4; j++) {
                __nv_bfloat16 hi = __float2bfloat16(vv[j]);
                Ah[m * K1_ASTR + k4 + j] = hi;
                Al[m * K1_ASTR + k4 + j] =
                    __float2bfloat16(vv[j] - __bfloat162float(hi));
            }
        }
        // W chunk 64x128 fp32 -> hi/lo
#pragma unroll
        for (int q = 0; q < 8; q++) {
            int f = tid + q * 256;              // 0..2047
            int k = f >> 5, n4 = (f & 31) * 4;
            float4 v = *(const float4*)&W[(size_t)(kt * 64 + k) * OUT_DIM + n4];
            float vv[4] = {v.x, v.y, v.z, v.w};
#pragma unroll
            for (int j = 0; j < 4; j++) {
                __nv_bfloat16 hi = __float2bfloat16(vv[j]);
                Wh[k * K1_WSTR + n4 + j] = hi;
                Wl[k * K1_WSTR + n4 + j] =
                    __float2bfloat16(vv[j] - __bfloat162float(hi));
            }
        }
        __syncthreads();

        u32 aH = (u32)__cvta_generic_to_shared(
            Ah + (wm * 32 + (lane & 15)) * K1_ASTR + (lane >> 4) * 8);
        u32 aL = (u32)__cvta_generic_to_shared(
            Al + (wm * 32 + (lane & 15)) * K1_ASTR + (lane >> 4) * 8);
        u32 bH = (u32)__cvta_generic_to_shared(
            Wh + (lane & 15) * K1_WSTR + wn * 32 + (lane >> 4) * 8);
        u32 bL = (u32)__cvta_generic_to_shared(
            Wl + (lane & 15) * K1_WSTR + wn * 32 + (lane >> 4) * 8);

#pragma unroll
        for (int k2 = 0; k2 < 4; k2++) {
            u32 ah[2][4], al[2][4], wh[4][2], wl[4][2];
#pragma unroll
            for (int mt = 0; mt < 2; mt++) {
                LDSM_X4(ah[mt][0], ah[mt][1], ah[mt][2], ah[mt][3],
                        aH + mt * 16 * (K1_ASTR * 2) + k2 * 32);
                LDSM_X4(al[mt][0], al[mt][1], al[mt][2], al[mt][3],
                        aL + mt * 16 * (K1_ASTR * 2) + k2 * 32);
            }
#pragma unroll
            for (int p = 0; p < 2; p++) {
                LDSM_X4T(wh[2 * p][0], wh[2 * p][1], wh[2 * p + 1][0],
                         wh[2 * p + 1][1],
                         bH + k2 * 16 * (K1_WSTR * 2) + p * 32);
                LDSM_X4T(wl[2 * p][0], wl[2 * p][1], wl[2 * p + 1][0],
                         wl[2 * p + 1][1],
                         bL + k2 * 16 * (K1_WSTR * 2) + p * 32);
            }
#pragma unroll
            for (int mt = 0; mt < 2; mt++)
#pragma unroll
                for (int nt = 0; nt < 4; nt++) {
                    MMA_OP(acc[mt][nt], ah[mt][0], ah[mt][1], ah[mt][2],
                           ah[mt][3], wh[nt][0], wh[nt][1]);
                    MMA_OP(acc[mt][nt], ah[mt][0], ah[mt][1], ah[mt][2],
                           ah[mt][3], wl[nt][0], wl[nt][1]);
                    MMA_OP(acc[mt][nt], al[mt][0], al[mt][1], al[mt][2],
                           al[mt][3], wh[nt][0], wh[nt][1]);
                }
        }
        __syncthreads();
    }

    // ---- epilogue: bias, a2 dot, exp, scale, store bf16 ----
    float hreg[2][4][4];
#pragma unroll
    for (int mt = 0; mt < 2; mt++) {
        float p0 = 0.f, p1 = 0.f;
#pragma unroll
        for (int nt = 0; nt < 4; nt++) {
            int c = wn * 32 + nt * 8 + (lane & 3) * 2;
            float2 bb = *(const float2*)&b[c];
            float2 aw = *(const float2*)&a2w[c];
            hreg[mt][nt][0] = acc[mt][nt][0] + bb.x;
            hreg[mt][nt][1] = acc[mt][nt][1] + bb.y;
            hreg[mt][nt][2] = acc[mt][nt][2] + bb.x;
            hreg[mt][nt][3] = acc[mt][nt][3] + bb.y;
            p0 = fmaf(hreg[mt][nt][0], aw.x, fmaf(hreg[mt][nt][1], aw.y, p0));
            p1 = fmaf(hreg[mt][nt][2], aw.x, fmaf(hreg[mt][nt][3], aw.y, p1));
        }
        p0 += __shfl_xor_sync(0xffffffffu, p0, 1);
        p0 += __shfl_xor_sync(0xffffffffu, p0, 2);
        p1 += __shfl_xor_sync(0xffffffffu, p1, 1);
        p1 += __shfl_xor_sync(0xffffffffu, p1, 2);
        if ((lane & 3) == 0) {
            int r = wm * 32 + mt * 16 + (lane >> 2);
            red[r * 4 + wn] = p0;
            red[(r + 8) * 4 + wn] = p1;
        }
    }
    __syncthreads();
    if (tid < 64) {
        float s = red[tid * 4] + red[tid * 4 + 1] + red[tid * 4 + 2] +
                  red[tid * 4 + 3] + a2b[0];
        float wv = expf(s);
        wrow[tid] = wv;
        g_P[(size_t)(m0 + tid) * PN + 128] = __float2bfloat16(wv);
    }
    // zero cols 129..135 (MMA reads them)
    if (tid < 64 * 7) {
        int r = tid / 7, c = 129 + tid % 7;
        g_P[(size_t)(m0 + r) * PN + c] = __float2bfloat16(0.f);
    }
    __syncthreads();
#pragma unroll
    for (int mt = 0; mt < 2; mt++) {
        int r0 = wm * 32 + mt * 16 + (lane >> 2);
        float w0 = wrow[r0], w1 = wrow[r0 + 8];
#pragma unroll
        for (int nt = 0; nt < 4; nt++) {
            int c = wn * 32 + nt * 8 + (lane & 3) * 2;
            *(__nv_bfloat162*)(g_P + (size_t)(m0 + r0) * PN + c) =
                __floats2bfloat162_rn(w0 * hreg[mt][nt][0],
                                      w0 * hreg[mt][nt][1]);
            *(__nv_bfloat162*)(g_P + (size_t)(m0 + r0 + 8) * PN + c) =
                __floats2bfloat162_rn(w1 * hreg[mt][nt][2],
                                      w1 * hreg[mt][nt][3]);
        }
    }
}

// ---------------------------------------------------------------------------
// Dummy kernel: aligns k3 onto ncu's profiled launch index (-s 5).
// ---------------------------------------------------------------------------
__global__ void kdummy() {}

// ---------------------------------------------------------------------------
// Kernel 3: Cpart[ks] = adjBF16[m0:+128, K-half] @ P[:, :136] via mma.sync.
// 64 Mtiles x 2 Ksplits = 128 CTAs, 8 warps (WM4 x WN2; wn0: 9 n8, wn1: 8 n8).
// A: LDG int32 -> 2-IMAD pack -> STS (2-stage). B: cp.async 4-stage, dist 3.
// ---------------------------------------------------------------------------
__global__ __launch_bounds__(256, 1) void k3_agg(const int* __restrict__ adj) {
    extern __shared__ __nv_bfloat16 smem[];
    __nv_bfloat16* Asm = smem;                  // 2 stages x [128][ASTR]
    __nv_bfloat16* Bsm = smem + 2 * AST_E;      // 4 stages x [64][BSTR]

    const int tid  = threadIdx.x;
    const int lane = tid & 31;
    const int warp = tid >> 5;
    const int wm   = warp & 3;    // rows wm*32..+32 (2 m16 tiles)
    const int wn   = warp >> 2;   // cols wn*72 (wn0: 9 tiles, wn1: 8 tiles)
    const int ntN  = 9 - wn;
    const int ks   = blockIdx.x & 1;
    const int m0   = (blockIdx.x >> 1) * BM3;

    const uint4* adjU4 = (const uint4*)adj;     // 2048 uint4 per adj row
    const size_t kbU4  = (size_t)ks * (KHALF / 4);

    u32 smbB = (u32)__cvta_generic_to_shared(Bsm);

    float acc[2][9][4];
#pragma unroll
    for (int mt = 0; mt < 2; mt++)
#pragma unroll
        for (int nt = 0; nt < 9; nt++)
#pragma unroll
            for (int j = 0; j < 4; j++) acc[mt][nt][j] = 0.f;

    uint4 aR[8];

    auto ldgA = [&](int it) {
#pragma unroll
        for (int q = 0; q < 8; q++) {
            int f = tid + q * 256;                       // 0..2047
            aR[q] = adjU4[(size_t)(m0 + (f >> 4)) * 2048 + kbU4 +
                          (size_t)it * 16 + (f & 15)];
        }
    };
    auto stsA = [&](int buf) {
        __nv_bfloat16* Ab = Asm + buf * AST_E;
#pragma unroll
        for (int q = 0; q < 8; q++) {
            int f = tid + q * 256;
            uint2 r;
            // {0,1} int32 pair -> packed bf16x2: (hi*65536+lo) * 0x3F80
            r.x = (aR[q].y * 65536u + aR[q].x) * 0x3F80u;
            r.y = (aR[q].w * 65536u + aR[q].z) * 0x3F80u;
            *(uint2*)(Ab + (f >> 4) * ASTR + (f & 15) * 4) = r;
        }
    };
    auto cpB = [&](int it, int s) {
        u32 bb = smbB + s * BST_E * 2;
#pragma unroll
        for (int q = 0; q < 5; q++) {
            int f = tid + q * 256;                       // need f < 1088
            if (f < 1088) {
                int r = f / 17, c = f % 17;
                const __nv_bfloat16* src =
                    g_P + (size_t)(ks * KHALF + it * 64 + r) * PN + c * 8;
                asm volatile("cp.async.cg.shared.global [%0], [%1], 16;"
                             :: "r"(bb + (u32)r * (BSTR * 2) + (u32)c * 16),
                                "l"(src) : "memory");
            }
        }
        asm volatile("cp.async.commit_group;" ::: "memory");
    };
    auto compute = [&](int abuf, int bst) {
        const __nv_bfloat16* Ab = Asm + abuf * AST_E + wm * 32 * ASTR;
        const __nv_bfloat16* Bb = Bsm + bst * BST_E + wn * 72;
        u32 aB = (u32)__cvta_generic_to_shared(
            Ab + (lane & 15) * ASTR + (lane >> 4) * 8);
        u32 bB = (u32)__cvta_generic_to_shared(
            Bb + (lane & 15) * BSTR + (lane >> 4) * 8);
        u32 b2 = (u32)__cvta_generic_to_shared(
            Bb + (lane & 15) * BSTR + 64);
#pragma unroll
        for (int k2 = 0; k2 < 4; k2++) {
            u32 a[2][4];
#pragma unroll
            for (int mt = 0; mt < 2; mt++)
                LDSM_X4(a[mt][0], a[mt][1], a[mt][2], a[mt][3],
                        aB + mt * 16 * (ASTR * 2) + k2 * 32);
            u32 bfr[9][2];
#pragma unroll
            for (int p = 0; p < 4; p++)
                LDSM_X4T(bfr[2 * p][0], bfr[2 * p][1], bfr[2 * p + 1][0],
                         bfr[2 * p + 1][1],
                         bB + k2 * 16 * (BSTR * 2) + p * 32);
            if (wn == 0)
                asm volatile(
                    "ldmatrix.sync.aligned.m8n8.x2.trans.shared.b16 "
                    "{%0,%1},[%2];"
                    : "=r"(bfr[8][0]), "=r"(bfr[8][1])
                    : "r"(b2 + k2 * 16 * (BSTR * 2)));
#pragma unroll
            for (int mt = 0; mt < 2; mt++)
#pragma unroll
                for (int nt = 0; nt < 9; nt++)
                    if (nt < ntN)
                        MMA_OP(acc[mt][nt], a[mt][0], a[mt][1], a[mt][2],
                               a[mt][3], bfr[nt][0], bfr[nt][1]);
        }
    };

    // -------- prologue --------
    cpB(0, 0);
    cpB(1, 1);
    cpB(2, 2);
    ldgA(0);
    stsA(0);
    ldgA(1);

    // -------- mainloop --------
#pragma unroll 1
    for (int it = 0; it < NIT; it++) {
        if (it <= NIT - 3)
            asm volatile("cp.async.wait_group 2;" ::: "memory");
        else if (it == NIT - 2)
            asm volatile("cp.async.wait_group 1;" ::: "memory");
        else
            asm volatile("cp.async.wait_group 0;" ::: "memory");
        __syncthreads();                         // tile(it) A+B visible
        if (it + 3 < NIT) cpB(it + 3, (it + 3) & 3);
        compute(it & 1, it & 3);
        if (it + 1 < NIT) stsA((it + 1) & 1);    // aR holds tile it+1
        if (it + 2 < NIT) ldgA(it + 2);
    }

    // -------- epilogue: write split-K partials --------
    float* dstB = g_C + (size_t)ks * N_NODES * PN;
#pragma unroll
    for (int mt = 0; mt < 2; mt++) {
        int r0 = m0 + wm * 32 + mt * 16 + (lane >> 2);
#pragma unroll
        for (int nt = 0; nt < 9; nt++)
            if (nt < ntN) {
                int c = wn * 72 + nt * 8 + (lane & 3) * 2;
                float* d0 = dstB + (size_t)r0 * PN + c;
                float* d1 = dstB + (size_t)(r0 + 8) * PN + c;
                d0[0] = acc[mt][nt][0];
                d0[1] = acc[mt][nt][1];
                d1[0] = acc[mt][nt][2];
                d1[1] = acc[mt][nt][3];
            }
    }
}

// ---------------------------------------------------------------------------
// Kernel 4: out = (C0 + C1)[:, :128] / (C0 + C1)[:, 128]
// ---------------------------------------------------------------------------
__global__ __launch_bounds__(256) void k4_div(float* __restrict__ out) {
    const int tid  = threadIdx.x;
    const int row  = blockIdx.x * 8 + (tid >> 5);
    const int lane = tid & 31;
    const float* c0 = g_C + (size_t)row * PN;
    const float* c1 = g_C + (size_t)(N_NODES + row) * PN;
    float4 v0 = *(const float4*)(c0 + lane * 4);
    float4 v1 = *(const float4*)(c1 + lane * 4);
    float inv = 1.0f / (c0[128] + c1[128]);
    float4 r;
    r.x = (v0.x + v1.x) * inv;
    r.y = (v0.y + v1.y) * inv;
    r.z = (v0.z + v1.z) * inv;
    r.w = (v0.w + v1.w) * inv;
    *(float4*)(out + (size_t)row * OUT_DIM + lane * 4) = r;
}

// ---------------------------------------------------------------------------
extern "C" void kernel_launch(void* const* d_in, const int* in_sizes, int n_in,
                              void* d_out, int out_size) {
    const float* F   = (const float*)d_in[0];
    const int*   adj = (const int*)d_in[1];
    const float* W   = (const float*)d_in[2];
    const float* b   = (const float*)d_in[3];
    // d_in[4], d_in[5] (a1_w, a1_b) cancel in the row softmax — unused.
    const float* a2w = (const float*)d_in[6];
    const float* a2b = (const float*)d_in[7];
    float* out = (float*)d_out;

    cudaFuncSetAttribute(k1t, cudaFuncAttributeMaxDynamicSharedMemorySize,
                         K1_SMEM);
    cudaFuncSetAttribute(k3_agg, cudaFuncAttributeMaxDynamicSharedMemorySize,
                         SM3);
    k1t<<<128, 256, K1_SMEM>>>(F, W, b, a2w, a2b);
    kdummy<<<1, 32>>>();               // shift k3 onto ncu's -s 5 slot
    kdummy<<<1, 32>>>();
    k3_agg<<<128, 256, SM3>>>(adj);
    k4_div<<<1024, 256>>>(out);
}